// round 15
// baseline (speedup 1.0000x reference)
#include <cuda_runtime.h>
#include <math.h>
#include <stdint.h>

#define B_ 16
#define N_ 1024
#define C_ 256

#define KC    32                   // k-chunk in floats (= 16 pairs)
#define KP    16                   // k-chunk in u32 pairs
#define STRU  20                   // smem row stride in u32 (16 data + 4 pad)
#define TILEU (128 * STRU)         // u32 per tile (10240 B)
#define DYN_BYTES (2 * 4 * TILEU * 4)   // 2 stages x 4 tiles = 81920 B

// packed bf16x2 hi/lo planes (u32 per k-pair)
static __device__ uint32_t g_Qhi[(size_t)B_ * N_ * C_ / 2];
static __device__ uint32_t g_Qlo[(size_t)B_ * N_ * C_ / 2];
static __device__ uint32_t g_Khi[(size_t)B_ * N_ * C_ / 2];
static __device__ uint32_t g_Klo[(size_t)B_ * N_ * C_ / 2];
static __device__ uint32_t g_Vthi[(size_t)B_ * C_ * N_ / 2];   // transposed [b][c][n/2]
static __device__ uint32_t g_Vtlo[(size_t)B_ * C_ * N_ / 2];
static __device__ uint32_t g_Phi[(size_t)B_ * N_ * N_ / 2];
static __device__ uint32_t g_Plo[(size_t)B_ * N_ * N_ / 2];

// ---------------------------------------------------------------------------
// mma.sync m16n8k16 bf16, row.col, fp32 accumulate
// ---------------------------------------------------------------------------
__device__ __forceinline__ void mma_bf16(float* d,
                                         uint32_t a0, uint32_t a1,
                                         uint32_t a2, uint32_t a3,
                                         uint32_t b0, uint32_t b1) {
    asm volatile(
        "mma.sync.aligned.m16n8k16.row.col.f32.bf16.bf16.f32 "
        "{%0,%1,%2,%3}, {%4,%5,%6,%7}, {%8,%9}, {%0,%1,%2,%3};"
        : "+f"(d[0]), "+f"(d[1]), "+f"(d[2]), "+f"(d[3])
        : "r"(a0), "r"(a1), "r"(a2), "r"(a3), "r"(b0), "r"(b1));
}

// split a float2 (k, k+1) into packed bf16x2 hi (exact trunc) and lo (RN)
__device__ __forceinline__ void pack_split(float2 v, uint32_t& hi, uint32_t& lo) {
    uint32_t u0 = __float_as_uint(v.x) & 0xFFFF0000u;
    uint32_t u1 = __float_as_uint(v.y) & 0xFFFF0000u;
    hi = __byte_perm(u0, u1, 0x7632);
    float l0 = v.x - __uint_as_float(u0);
    float l1 = v.y - __uint_as_float(u1);
    asm("cvt.rn.bf16x2.f32 %0, %1, %2;" : "=r"(lo) : "f"(l1), "f"(l0));
}

// ---------------------------------------------------------------------------
// cp.async 16B
// ---------------------------------------------------------------------------
__device__ __forceinline__ void cp16(uint32_t saddr, const uint32_t* g) {
    asm volatile("cp.async.ca.shared.global [%0], [%1], 16;"
                 :: "r"(saddr), "l"(g) : "memory");
}

// load 4 planes (Ahi, Alo, Bhi, Blo) of one chunk into one stage
__device__ __forceinline__ void load_tiles_async(
    const uint32_t* __restrict__ Ahi_g, const uint32_t* __restrict__ Alo_g,
    const uint32_t* __restrict__ Bhi_g, const uint32_t* __restrict__ Blo_g,
    int ldaP, int ldbP, int aBase, int bBase, int k0P,
    uint32_t sbase, int tid)
{
    const uint32_t* planes[4] = { Ahi_g, Alo_g, Bhi_g, Blo_g };
#pragma unroll
    for (int e = 0; e < 8; e++) {
        int lin  = tid + e * 256;          // 0..2047
        int t    = lin >> 9;               // tile 0..3
        int rem  = lin & 511;
        int row  = rem >> 2;               // 0..127
        int cc   = (rem & 3) * 4;          // u32 col 0,4,8,12
        int base = (t < 2) ? aBase : bBase;
        int ldp  = (t < 2) ? ldaP : ldbP;
        uint32_t dst = sbase + (uint32_t)(t * TILEU + row * STRU + cc) * 4;
        cp16(dst, planes[t] + (size_t)(base + row) * ldp + k0P + cc);
    }
    asm volatile("cp.async.commit_group;" ::: "memory");
}

// ---------------------------------------------------------------------------
// one k-chunk (16 pairs): pure LDS + MMA, 3-pass bf16
// 8 warps (2x4), warp tile 64x32, 4x4 m16n8 tiles
// ---------------------------------------------------------------------------
__device__ __forceinline__ void compute_chunk(
    const uint32_t* __restrict__ Ahi, const uint32_t* __restrict__ Alo,
    const uint32_t* __restrict__ Bhi, const uint32_t* __restrict__ Blo,
    float acc[4][4][4], int wm, int wn, int g, int cq)
{
#pragma unroll
    for (int s8 = 0; s8 < KP; s8 += 8) {
        const int co = s8 + cq;
        uint32_t ah[4][4], al[4][4];
#pragma unroll
        for (int i = 0; i < 4; i++) {
            int r0 = (wm * 64 + i * 16 + g) * STRU + co;
            int r1 = r0 + 8 * STRU;
            ah[i][0] = Ahi[r0];     al[i][0] = Alo[r0];
            ah[i][1] = Ahi[r1];     al[i][1] = Alo[r1];
            ah[i][2] = Ahi[r0 + 4]; al[i][2] = Alo[r0 + 4];
            ah[i][3] = Ahi[r1 + 4]; al[i][3] = Alo[r1 + 4];
        }
#pragma unroll
        for (int j = 0; j < 4; j++) {
            int rb = (wn * 32 + j * 8 + g) * STRU + co;
            uint32_t bh0 = Bhi[rb], bh1 = Bhi[rb + 4];
            uint32_t bl0 = Blo[rb], bl1 = Blo[rb + 4];
#pragma unroll
            for (int i = 0; i < 4; i++)
                mma_bf16(acc[i][j], ah[i][0], ah[i][1], ah[i][2], ah[i][3], bh0, bh1);
#pragma unroll
            for (int i = 0; i < 4; i++)
                mma_bf16(acc[i][j], al[i][0], al[i][1], al[i][2], al[i][3], bh0, bh1);
#pragma unroll
            for (int i = 0; i < 4; i++)
                mma_bf16(acc[i][j], ah[i][0], ah[i][1], ah[i][2], ah[i][3], bl0, bl1);
        }
    }
}

// ---------------------------------------------------------------------------
// 2-stage cp.async mainloop
// ---------------------------------------------------------------------------
__device__ __forceinline__ void gemm_mainloop(
    const uint32_t* __restrict__ Ahi_g, const uint32_t* __restrict__ Alo_g,
    const uint32_t* __restrict__ Bhi_g, const uint32_t* __restrict__ Blo_g,
    int ldaP, int ldbP, int aBase, int bBase, int nChunks,
    uint32_t* __restrict__ smem, uint32_t sbase,
    float acc[4][4][4], int tid, int wm, int wn, int g, int cq)
{
    load_tiles_async(Ahi_g, Alo_g, Bhi_g, Blo_g, ldaP, ldbP,
                     aBase, bBase, 0, sbase, tid);

    for (int c = 0; c < nChunks; c++) {
        const int cur = c & 1;
        if (c + 1 < nChunks) {
            const int nxt = cur ^ 1;
            load_tiles_async(Ahi_g, Alo_g, Bhi_g, Blo_g, ldaP, ldbP,
                             aBase, bBase, (c + 1) * KP,
                             sbase + (uint32_t)(nxt * 4 * TILEU) * 4, tid);
            asm volatile("cp.async.wait_group 1;" ::: "memory");
        } else {
            asm volatile("cp.async.wait_group 0;" ::: "memory");
        }
        __syncthreads();
        const uint32_t* st = smem + cur * 4 * TILEU;
        compute_chunk(st, st + TILEU, st + 2 * TILEU, st + 3 * TILEU,
                      acc, wm, wn, g, cq);
        __syncthreads();
    }
}

// ---------------------------------------------------------------------------
// Kernel A: pack Q and K into hi/lo planes
// ---------------------------------------------------------------------------
__global__ __launch_bounds__(256) void pack_qk_kernel(
    const float* __restrict__ Q, const float* __restrict__ K)
{
    size_t idx = (size_t)blockIdx.x * 256 + threadIdx.x;   // float4 index
    const size_t total = (size_t)B_ * N_ * C_ / 4;
    if (idx >= total) return;
    float4 q = *reinterpret_cast<const float4*>(Q + idx * 4);
    float4 k = *reinterpret_cast<const float4*>(K + idx * 4);
    uint32_t h0, l0, h1, l1;
    pack_split(make_float2(q.x, q.y), h0, l0);
    pack_split(make_float2(q.z, q.w), h1, l1);
    *reinterpret_cast<uint2*>(&g_Qhi[idx * 2]) = make_uint2(h0, h1);
    *reinterpret_cast<uint2*>(&g_Qlo[idx * 2]) = make_uint2(l0, l1);
    pack_split(make_float2(k.x, k.y), h0, l0);
    pack_split(make_float2(k.z, k.w), h1, l1);
    *reinterpret_cast<uint2*>(&g_Khi[idx * 2]) = make_uint2(h0, h1);
    *reinterpret_cast<uint2*>(&g_Klo[idx * 2]) = make_uint2(l0, l1);
}

// ---------------------------------------------------------------------------
// Kernel B: transpose V -> packed hi/lo planes [b][c][n/2]
// ---------------------------------------------------------------------------
__global__ __launch_bounds__(256) void transpose_v_kernel(const float* __restrict__ V)
{
    __shared__ float t[32][33];
    const int b  = blockIdx.z;
    const int n0 = blockIdx.y * 32;
    const int c0 = blockIdx.x * 32;
    const float* Vb = V + (size_t)b * N_ * C_;
    const int x = threadIdx.x & 31;
    const int y = threadIdx.x >> 5;            // 0..7
#pragma unroll
    for (int dy = 0; dy < 32; dy += 8)
        t[y + dy][x] = Vb[(size_t)(n0 + y + dy) * C_ + c0 + x];
    __syncthreads();
    const int tid = threadIdx.x;
#pragma unroll
    for (int e = 0; e < 2; e++) {
        int idx = tid + e * 256;               // 0..511
        int cl  = idx >> 4;                    // 0..31 c within tile
        int p   = idx & 15;                    // 0..15 n-pair within tile
        float2 v = make_float2(t[2 * p][cl], t[2 * p + 1][cl]);
        uint32_t h, l;
        pack_split(v, h, l);
        size_t o = ((size_t)b * C_ + c0 + cl) * (N_ / 2) + n0 / 2 + p;
        g_Vthi[o] = h;
        g_Vtlo[o] = l;
    }
}

// ---------------------------------------------------------------------------
// Kernel 1: attn = masked((Q K^T + dis) * 0.0625)
// ---------------------------------------------------------------------------
__global__ __launch_bounds__(256, 2) void qk_scores_kernel(
    const float* __restrict__ dis,
    const int*   __restrict__ mask,
    float* __restrict__ attn)
{
    extern __shared__ uint32_t smem[];
    const uint32_t sbase = (uint32_t)__cvta_generic_to_shared(smem);

    const int b     = blockIdx.z;
    const int qBase = blockIdx.y * 128;
    const int kBase = blockIdx.x * 128;

    const int tid  = threadIdx.x;
    const int lane = tid & 31;
    const int w    = tid >> 5;
    const int wm   = w >> 2;
    const int wn   = w & 3;
    const int g    = lane >> 2;
    const int cq   = lane & 3;

    float acc[4][4][4];
#pragma unroll
    for (int i = 0; i < 4; i++)
#pragma unroll
        for (int j = 0; j < 4; j++)
#pragma unroll
            for (int r = 0; r < 4; r++) acc[i][j][r] = 0.0f;

    const size_t off = (size_t)b * N_ * (C_ / 2);
    gemm_mainloop(g_Qhi + off, g_Qlo + off, g_Khi + off, g_Klo + off,
                  C_ / 2, C_ / 2, qBase, kBase, C_ / KC,
                  smem, sbase, acc, tid, wm, wn, g, cq);

#pragma unroll
    for (int i = 0; i < 4; i++) {
        int r0 = qBase + wm * 64 + i * 16 + g;
        int r1 = r0 + 8;
#pragma unroll
        for (int j = 0; j < 4; j++) {
            int col = kBase + wn * 32 + j * 8 + 2 * cq;
            size_t i0 = ((size_t)b * N_ + r0) * N_ + col;
            size_t i1 = ((size_t)b * N_ + r1) * N_ + col;
            float2 d0 = *reinterpret_cast<const float2*>(&dis[i0]);
            float2 d1 = *reinterpret_cast<const float2*>(&dis[i1]);
            int2   m0 = *reinterpret_cast<const int2*>(&mask[i0]);
            int2   m1 = *reinterpret_cast<const int2*>(&mask[i1]);
            float2 o0, o1;
            o0.x = m0.x ? -INFINITY : (acc[i][j][0] + d0.x) * 0.0625f;
            o0.y = m0.y ? -INFINITY : (acc[i][j][1] + d0.y) * 0.0625f;
            o1.x = m1.x ? -INFINITY : (acc[i][j][2] + d1.x) * 0.0625f;
            o1.y = m1.y ? -INFINITY : (acc[i][j][3] + d1.y) * 0.0625f;
            *reinterpret_cast<float2*>(&attn[i0]) = o0;
            *reinterpret_cast<float2*>(&attn[i1]) = o1;
        }
    }
}

// ---------------------------------------------------------------------------
// Kernel 2: row softmax; writes fp32 p_attn AND packed hi/lo planes of P
// ---------------------------------------------------------------------------
__global__ __launch_bounds__(256) void softmax_kernel(float* __restrict__ attn)
{
    __shared__ float s1[8], s2[8];
    const size_t base = (size_t)blockIdx.x * N_;
    const int t = threadIdx.x;
    const int w = t >> 5, lane = t & 31;

    float4 v = *reinterpret_cast<const float4*>(&attn[base + t * 4]);

    float m = fmaxf(fmaxf(v.x, v.y), fmaxf(v.z, v.w));
#pragma unroll
    for (int o = 16; o; o >>= 1) m = fmaxf(m, __shfl_xor_sync(0xffffffffu, m, o));
    if (lane == 0) s1[w] = m;
    __syncthreads();
    float M = s1[0];
#pragma unroll
    for (int i = 1; i < 8; i++) M = fmaxf(M, s1[i]);

    float4 p;
    p.x = __expf(v.x - M); p.y = __expf(v.y - M);
    p.z = __expf(v.z - M); p.w = __expf(v.w - M);
    float s = (p.x + p.y) + (p.z + p.w);
#pragma unroll
    for (int o = 16; o; o >>= 1) s += __shfl_xor_sync(0xffffffffu, s, o);
    if (lane == 0) s2[w] = s;
    __syncthreads();
    float S = s2[0];
#pragma unroll
    for (int i = 1; i < 8; i++) S += s2[i];
    float inv = 1.0f / S;

    p.x *= inv; p.y *= inv; p.z *= inv; p.w *= inv;
    *reinterpret_cast<float4*>(&attn[base + t * 4]) = p;

    uint32_t h0, l0, h1, l1;
    pack_split(make_float2(p.x, p.y), h0, l0);
    pack_split(make_float2(p.z, p.w), h1, l1);
    size_t po = base / 2 + (size_t)t * 2;
    *reinterpret_cast<uint2*>(&g_Phi[po]) = make_uint2(h0, h1);
    *reinterpret_cast<uint2*>(&g_Plo[po]) = make_uint2(l0, l1);
}

// ---------------------------------------------------------------------------
// Kernel 3: p_val = p_attn @ V
// ---------------------------------------------------------------------------
__global__ __launch_bounds__(256, 2) void pv_kernel(float* __restrict__ out)
{
    extern __shared__ uint32_t smem[];
    const uint32_t sbase = (uint32_t)__cvta_generic_to_shared(smem);

    const int b     = blockIdx.z;
    const int qBase = blockIdx.y * 128;
    const int nBase = blockIdx.x * 128;

    const int tid  = threadIdx.x;
    const int lane = tid & 31;
    const int w    = tid >> 5;
    const int wm   = w >> 2;
    const int wn   = w & 3;
    const int g    = lane >> 2;
    const int cq   = lane & 3;

    float acc[4][4][4];
#pragma unroll
    for (int i = 0; i < 4; i++)
#pragma unroll
        for (int j = 0; j < 4; j++)
#pragma unroll
            for (int r = 0; r < 4; r++) acc[i][j][r] = 0.0f;

    const size_t pOff = (size_t)b * N_ * (N_ / 2);
    const size_t vOff = (size_t)b * C_ * (N_ / 2);
    gemm_mainloop(g_Phi + pOff, g_Plo + pOff, g_Vthi + vOff, g_Vtlo + vOff,
                  N_ / 2, N_ / 2, qBase, nBase, N_ / KC,
                  smem, sbase, acc, tid, wm, wn, g, cq);

#pragma unroll
    for (int i = 0; i < 4; i++) {
        int r0 = qBase + wm * 64 + i * 16 + g;
        int r1 = r0 + 8;
#pragma unroll
        for (int j = 0; j < 4; j++) {
            int col = nBase + wn * 32 + j * 8 + 2 * cq;
            size_t i0 = ((size_t)b * N_ + r0) * C_ + col;
            size_t i1 = ((size_t)b * N_ + r1) * C_ + col;
            *reinterpret_cast<float2*>(&out[i0]) = make_float2(acc[i][j][0], acc[i][j][1]);
            *reinterpret_cast<float2*>(&out[i1]) = make_float2(acc[i][j][2], acc[i][j][3]);
        }
    }
}

// ---------------------------------------------------------------------------
// Launch
// ---------------------------------------------------------------------------
extern "C" void kernel_launch(void* const* d_in, const int* in_sizes, int n_in,
                              void* d_out, int out_size)
{
    const float* Q    = (const float*)d_in[0];
    const float* K    = (const float*)d_in[1];
    const float* V    = (const float*)d_in[2];
    const int*   mask = (const int*)d_in[3];
    const float* dis  = (const float*)d_in[4];

    float* out    = (float*)d_out;
    float* p_val  = out;                          // [B, N, C]
    float* p_attn = out + (size_t)B_ * N_ * C_;   // [B, N, N]

    cudaFuncSetAttribute(qk_scores_kernel,
                         cudaFuncAttributeMaxDynamicSharedMemorySize, DYN_BYTES);
    cudaFuncSetAttribute(pv_kernel,
                         cudaFuncAttributeMaxDynamicSharedMemorySize, DYN_BYTES);

    const int packBlocks = (B_ * N_ * C_ / 4 + 255) / 256;
    pack_qk_kernel<<<packBlocks, 256>>>(Q, K);
    transpose_v_kernel<<<dim3(C_ / 32, N_ / 32, B_), 256>>>(V);
    qk_scores_kernel<<<dim3(N_ / 128, N_ / 128, B_), 256, DYN_BYTES>>>(dis, mask, p_attn);
    softmax_kernel<<<B_ * N_, 256>>>(p_attn);
    pv_kernel<<<dim3(C_ / 128, N_ / 128, B_), 256, DYN_BYTES>>>(p_val);
}

// round 16
// speedup vs baseline: 1.0813x; 1.0813x over previous
#include <cuda_runtime.h>
#include <cuda_fp16.h>
#include <math.h>
#include <stdint.h>

#define B_ 16
#define N_ 1024
#define C_ 256

#define KC    32                   // k-chunk in floats (= 16 pairs)
#define KP    16                   // k-chunk in u32 pairs
#define STRU  20                   // plane smem row stride in u32
#define TILEU (128 * STRU)         // u32 per plane tile (10240 B)
#define STRF  36                   // fp32 smem row stride (floats)
#define TILEF (128 * STRF)         // floats per fp32 tile (18432 B)

#define DYN_QK (2 * 4 * TILEU * 4)                      // 81920 B
#define PV_STAGE_U (TILEF + 2 * TILEU)                  // 9728 u32
#define DYN_PV (2 * PV_STAGE_U * 4)                     // 77824 B

// packed bf16x2 hi/lo planes for Q, K (u32 per k-pair)
static __device__ uint32_t g_Qhi[(size_t)B_ * N_ * C_ / 2];
static __device__ uint32_t g_Qlo[(size_t)B_ * N_ * C_ / 2];
static __device__ uint32_t g_Khi[(size_t)B_ * N_ * C_ / 2];
static __device__ uint32_t g_Klo[(size_t)B_ * N_ * C_ / 2];
// packed fp16x2 hi/lo planes for transposed V [b][c][n/2]
static __device__ uint32_t g_Vthi[(size_t)B_ * C_ * N_ / 2];
static __device__ uint32_t g_Vtlo[(size_t)B_ * C_ * N_ / 2];

// ---------------------------------------------------------------------------
// mma intrinsics
// ---------------------------------------------------------------------------
__device__ __forceinline__ void mma_bf16(float* d,
                                         uint32_t a0, uint32_t a1,
                                         uint32_t a2, uint32_t a3,
                                         uint32_t b0, uint32_t b1) {
    asm volatile(
        "mma.sync.aligned.m16n8k16.row.col.f32.bf16.bf16.f32 "
        "{%0,%1,%2,%3}, {%4,%5,%6,%7}, {%8,%9}, {%0,%1,%2,%3};"
        : "+f"(d[0]), "+f"(d[1]), "+f"(d[2]), "+f"(d[3])
        : "r"(a0), "r"(a1), "r"(a2), "r"(a3), "r"(b0), "r"(b1));
}

__device__ __forceinline__ void mma_fp16(float* d,
                                         uint32_t a0, uint32_t a1,
                                         uint32_t a2, uint32_t a3,
                                         uint32_t b0, uint32_t b1) {
    asm volatile(
        "mma.sync.aligned.m16n8k16.row.col.f32.f16.f16.f32 "
        "{%0,%1,%2,%3}, {%4,%5,%6,%7}, {%8,%9}, {%0,%1,%2,%3};"
        : "+f"(d[0]), "+f"(d[1]), "+f"(d[2]), "+f"(d[3])
        : "r"(a0), "r"(a1), "r"(a2), "r"(a3), "r"(b0), "r"(b1));
}

// bf16 split: hi exact trunc, lo RN
__device__ __forceinline__ void pack_split_bf16(float2 v, uint32_t& hi, uint32_t& lo) {
    uint32_t u0 = __float_as_uint(v.x) & 0xFFFF0000u;
    uint32_t u1 = __float_as_uint(v.y) & 0xFFFF0000u;
    hi = __byte_perm(u0, u1, 0x7632);
    float l0 = v.x - __uint_as_float(u0);
    float l1 = v.y - __uint_as_float(u1);
    asm("cvt.rn.bf16x2.f32 %0, %1, %2;" : "=r"(lo) : "f"(l1), "f"(l0));
}

// fp32 pair -> packed f16x2 (low half = v.x)
__device__ __forceinline__ uint32_t cvt_f16x2(float2 v) {
    uint32_t r;
    asm("cvt.rn.f16x2.f32 %0, %1, %2;" : "=r"(r) : "f"(v.y), "f"(v.x));
    return r;
}

// ---------------------------------------------------------------------------
// cp.async 16B
// ---------------------------------------------------------------------------
__device__ __forceinline__ void cp16(uint32_t saddr, const void* g) {
    asm volatile("cp.async.ca.shared.global [%0], [%1], 16;"
                 :: "r"(saddr), "l"(g) : "memory");
}

// ===========================================================================
// QK path (pre-packed bf16 planes, 3-pass) — identical to validated R15
// ===========================================================================
__device__ __forceinline__ void qk_load_async(
    const uint32_t* __restrict__ Ahi_g, const uint32_t* __restrict__ Alo_g,
    const uint32_t* __restrict__ Bhi_g, const uint32_t* __restrict__ Blo_g,
    int ldP, int aBase, int bBase, int k0P, uint32_t sbase, int tid)
{
    const uint32_t* planes[4] = { Ahi_g, Alo_g, Bhi_g, Blo_g };
#pragma unroll
    for (int e = 0; e < 8; e++) {
        int lin  = tid + e * 256;
        int t    = lin >> 9;
        int rem  = lin & 511;
        int row  = rem >> 2;
        int cc   = (rem & 3) * 4;
        int base = (t < 2) ? aBase : bBase;
        uint32_t dst = sbase + (uint32_t)(t * TILEU + row * STRU + cc) * 4;
        cp16(dst, planes[t] + (size_t)(base + row) * ldP + k0P + cc);
    }
    asm volatile("cp.async.commit_group;" ::: "memory");
}

__device__ __forceinline__ void qk_compute_chunk(
    const uint32_t* __restrict__ Ahi, const uint32_t* __restrict__ Alo,
    const uint32_t* __restrict__ Bhi, const uint32_t* __restrict__ Blo,
    float acc[4][4][4], int wm, int wn, int g, int cq)
{
#pragma unroll
    for (int s8 = 0; s8 < KP; s8 += 8) {
        const int co = s8 + cq;
        uint32_t ah[4][4], al[4][4];
#pragma unroll
        for (int i = 0; i < 4; i++) {
            int r0 = (wm * 64 + i * 16 + g) * STRU + co;
            int r1 = r0 + 8 * STRU;
            ah[i][0] = Ahi[r0];     al[i][0] = Alo[r0];
            ah[i][1] = Ahi[r1];     al[i][1] = Alo[r1];
            ah[i][2] = Ahi[r0 + 4]; al[i][2] = Alo[r0 + 4];
            ah[i][3] = Ahi[r1 + 4]; al[i][3] = Alo[r1 + 4];
        }
#pragma unroll
        for (int j = 0; j < 4; j++) {
            int rb = (wn * 32 + j * 8 + g) * STRU + co;
            uint32_t bh0 = Bhi[rb], bh1 = Bhi[rb + 4];
            uint32_t bl0 = Blo[rb], bl1 = Blo[rb + 4];
#pragma unroll
            for (int i = 0; i < 4; i++)
                mma_bf16(acc[i][j], ah[i][0], ah[i][1], ah[i][2], ah[i][3], bh0, bh1);
#pragma unroll
            for (int i = 0; i < 4; i++)
                mma_bf16(acc[i][j], al[i][0], al[i][1], al[i][2], al[i][3], bh0, bh1);
#pragma unroll
            for (int i = 0; i < 4; i++)
                mma_bf16(acc[i][j], ah[i][0], ah[i][1], ah[i][2], ah[i][3], bl0, bl1);
        }
    }
}

// ---------------------------------------------------------------------------
// Kernel A: pack Q and K into bf16 hi/lo planes
// ---------------------------------------------------------------------------
__global__ __launch_bounds__(256) void pack_qk_kernel(
    const float* __restrict__ Q, const float* __restrict__ K)
{
    size_t idx = (size_t)blockIdx.x * 256 + threadIdx.x;
    const size_t total = (size_t)B_ * N_ * C_ / 4;
    if (idx >= total) return;
    float4 q = *reinterpret_cast<const float4*>(Q + idx * 4);
    float4 k = *reinterpret_cast<const float4*>(K + idx * 4);
    uint32_t h0, l0, h1, l1;
    pack_split_bf16(make_float2(q.x, q.y), h0, l0);
    pack_split_bf16(make_float2(q.z, q.w), h1, l1);
    *reinterpret_cast<uint2*>(&g_Qhi[idx * 2]) = make_uint2(h0, h1);
    *reinterpret_cast<uint2*>(&g_Qlo[idx * 2]) = make_uint2(l0, l1);
    pack_split_bf16(make_float2(k.x, k.y), h0, l0);
    pack_split_bf16(make_float2(k.z, k.w), h1, l1);
    *reinterpret_cast<uint2*>(&g_Khi[idx * 2]) = make_uint2(h0, h1);
    *reinterpret_cast<uint2*>(&g_Klo[idx * 2]) = make_uint2(l0, l1);
}

// ---------------------------------------------------------------------------
// Kernel B: transpose V -> fp16 hi/lo planes [b][c][n/2]
// ---------------------------------------------------------------------------
__global__ __launch_bounds__(256) void transpose_v_kernel(const float* __restrict__ V)
{
    __shared__ float t[32][33];
    const int b  = blockIdx.z;
    const int n0 = blockIdx.y * 32;
    const int c0 = blockIdx.x * 32;
    const float* Vb = V + (size_t)b * N_ * C_;
    const int x = threadIdx.x & 31;
    const int y = threadIdx.x >> 5;
#pragma unroll
    for (int dy = 0; dy < 32; dy += 8)
        t[y + dy][x] = Vb[(size_t)(n0 + y + dy) * C_ + c0 + x];
    __syncthreads();
    const int tid = threadIdx.x;
#pragma unroll
    for (int e = 0; e < 2; e++) {
        int idx = tid + e * 256;
        int cl  = idx >> 4;
        int p   = idx & 15;
        float vx = t[2 * p][cl], vy = t[2 * p + 1][cl];
        __half hx = __float2half_rn(vx), hy = __float2half_rn(vy);
        float lx = vx - __half2float(hx);
        float ly = vy - __half2float(hy);
        __half2 hp = __halves2half2(hx, hy);
        __half2 lp = __halves2half2(__float2half_rn(lx), __float2half_rn(ly));
        size_t o = ((size_t)b * C_ + c0 + cl) * (N_ / 2) + n0 / 2 + p;
        g_Vthi[o] = *reinterpret_cast<uint32_t*>(&hp);
        g_Vtlo[o] = *reinterpret_cast<uint32_t*>(&lp);
    }
}

// ---------------------------------------------------------------------------
// Kernel 1: attn = masked((Q K^T + dis) * 0.0625)
// ---------------------------------------------------------------------------
__global__ __launch_bounds__(256, 2) void qk_scores_kernel(
    const float* __restrict__ dis,
    const int*   __restrict__ mask,
    float* __restrict__ attn)
{
    extern __shared__ uint32_t smem[];
    const uint32_t sbase = (uint32_t)__cvta_generic_to_shared(smem);

    const int b     = blockIdx.z;
    const int qBase = blockIdx.y * 128;
    const int kBase = blockIdx.x * 128;

    const int tid  = threadIdx.x;
    const int lane = tid & 31;
    const int w    = tid >> 5;
    const int wm   = w >> 2;
    const int wn   = w & 3;
    const int g    = lane >> 2;
    const int cq   = lane & 3;

    float acc[4][4][4];
#pragma unroll
    for (int i = 0; i < 4; i++)
#pragma unroll
        for (int j = 0; j < 4; j++)
#pragma unroll
            for (int r = 0; r < 4; r++) acc[i][j][r] = 0.0f;

    const size_t off = (size_t)b * N_ * (C_ / 2);
    const uint32_t* Qhi = g_Qhi + off;
    const uint32_t* Qlo = g_Qlo + off;
    const uint32_t* Khi = g_Khi + off;
    const uint32_t* Klo = g_Klo + off;
    const int nChunks = C_ / KC;

    qk_load_async(Qhi, Qlo, Khi, Klo, C_ / 2, qBase, kBase, 0, sbase, tid);
    for (int c = 0; c < nChunks; c++) {
        const int cur = c & 1;
        if (c + 1 < nChunks) {
            const int nxt = cur ^ 1;
            qk_load_async(Qhi, Qlo, Khi, Klo, C_ / 2, qBase, kBase, (c + 1) * KP,
                          sbase + (uint32_t)(nxt * 4 * TILEU) * 4, tid);
            asm volatile("cp.async.wait_group 1;" ::: "memory");
        } else {
            asm volatile("cp.async.wait_group 0;" ::: "memory");
        }
        __syncthreads();
        const uint32_t* st = smem + cur * 4 * TILEU;
        qk_compute_chunk(st, st + TILEU, st + 2 * TILEU, st + 3 * TILEU,
                         acc, wm, wn, g, cq);
        __syncthreads();
    }

#pragma unroll
    for (int i = 0; i < 4; i++) {
        int r0 = qBase + wm * 64 + i * 16 + g;
        int r1 = r0 + 8;
#pragma unroll
        for (int j = 0; j < 4; j++) {
            int col = kBase + wn * 32 + j * 8 + 2 * cq;
            size_t i0 = ((size_t)b * N_ + r0) * N_ + col;
            size_t i1 = ((size_t)b * N_ + r1) * N_ + col;
            float2 d0 = *reinterpret_cast<const float2*>(&dis[i0]);
            float2 d1 = *reinterpret_cast<const float2*>(&dis[i1]);
            int2   m0 = *reinterpret_cast<const int2*>(&mask[i0]);
            int2   m1 = *reinterpret_cast<const int2*>(&mask[i1]);
            float2 o0, o1;
            o0.x = m0.x ? -INFINITY : (acc[i][j][0] + d0.x) * 0.0625f;
            o0.y = m0.y ? -INFINITY : (acc[i][j][1] + d0.y) * 0.0625f;
            o1.x = m1.x ? -INFINITY : (acc[i][j][2] + d1.x) * 0.0625f;
            o1.y = m1.y ? -INFINITY : (acc[i][j][3] + d1.y) * 0.0625f;
            *reinterpret_cast<float2*>(&attn[i0]) = o0;
            *reinterpret_cast<float2*>(&attn[i1]) = o1;
        }
    }
}

// ---------------------------------------------------------------------------
// Kernel 2: row softmax (rows of 1024), shuffle-based, float4 I/O
// ---------------------------------------------------------------------------
__global__ __launch_bounds__(256) void softmax_kernel(float* __restrict__ attn)
{
    __shared__ float s1[8], s2[8];
    const size_t base = (size_t)blockIdx.x * N_;
    const int t = threadIdx.x;
    const int w = t >> 5, lane = t & 31;

    float4 v = *reinterpret_cast<const float4*>(&attn[base + t * 4]);

    float m = fmaxf(fmaxf(v.x, v.y), fmaxf(v.z, v.w));
#pragma unroll
    for (int o = 16; o; o >>= 1) m = fmaxf(m, __shfl_xor_sync(0xffffffffu, m, o));
    if (lane == 0) s1[w] = m;
    __syncthreads();
    float M = s1[0];
#pragma unroll
    for (int i = 1; i < 8; i++) M = fmaxf(M, s1[i]);

    float4 p;
    p.x = __expf(v.x - M); p.y = __expf(v.y - M);
    p.z = __expf(v.z - M); p.w = __expf(v.w - M);
    float s = (p.x + p.y) + (p.z + p.w);
#pragma unroll
    for (int o = 16; o; o >>= 1) s += __shfl_xor_sync(0xffffffffu, s, o);
    if (lane == 0) s2[w] = s;
    __syncthreads();
    float S = s2[0];
#pragma unroll
    for (int i = 1; i < 8; i++) S += s2[i];
    float inv = 1.0f / S;

    p.x *= inv; p.y *= inv; p.z *= inv; p.w *= inv;
    *reinterpret_cast<float4*>(&attn[base + t * 4]) = p;
}

// ===========================================================================
// PV path: A = softmaxed attn (fp32, cvt to fp16 in-loop), B = V fp16 planes
// 2 MMA passes: acc += P*Vhi + P*Vlo
// ===========================================================================
__device__ __forceinline__ void pv_load_async(
    const float* __restrict__ Pg, const uint32_t* __restrict__ Vhi_g,
    const uint32_t* __restrict__ Vlo_g,
    int qBase, int nBase, int k0, uint32_t sbase, int tid)
{
    // A: 128 rows x 32 floats (fp32) at stage offset 0
#pragma unroll
    for (int e = 0; e < 4; e++) {
        int lin = tid + e * 256;
        int row = lin >> 3;
        int c4  = (lin & 7) * 4;
        uint32_t dst = sbase + (uint32_t)(row * STRF + c4) * 4;
        cp16(dst, &Pg[(size_t)(qBase + row) * N_ + k0 + c4]);
    }
    // B: 2 planes x 128 rows x 16 u32 at stage offset TILEF
    const uint32_t* planes[2] = { Vhi_g, Vlo_g };
#pragma unroll
    for (int e = 0; e < 4; e++) {
        int lin  = tid + e * 256;          // 0..1023
        int t    = lin >> 9;               // plane 0..1
        int rem  = lin & 511;
        int row  = rem >> 2;
        int cc   = (rem & 3) * 4;
        uint32_t dst = sbase + (uint32_t)(TILEF + t * TILEU + row * STRU + cc) * 4;
        cp16(dst, planes[t] + (size_t)(nBase + row) * (N_ / 2) + k0 / 2 + cc);
    }
    asm volatile("cp.async.commit_group;" ::: "memory");
}

__device__ __forceinline__ void pv_compute_chunk(
    const float* __restrict__ As, const uint32_t* __restrict__ Vhi,
    const uint32_t* __restrict__ Vlo,
    float acc[4][4][4], int wm, int wn, int g, int cq)
{
#pragma unroll
    for (int s = 0; s < KC; s += 16) {
        const int co = s + 2 * cq;
        const int s8 = s / 2;
        uint32_t a[4][4];
#pragma unroll
        for (int i = 0; i < 4; i++) {
            int r0 = (wm * 64 + i * 16 + g) * STRF + co;
            int r1 = r0 + 8 * STRF;
            a[i][0] = cvt_f16x2(*reinterpret_cast<const float2*>(&As[r0]));
            a[i][1] = cvt_f16x2(*reinterpret_cast<const float2*>(&As[r1]));
            a[i][2] = cvt_f16x2(*reinterpret_cast<const float2*>(&As[r0 + 8]));
            a[i][3] = cvt_f16x2(*reinterpret_cast<const float2*>(&As[r1 + 8]));
        }
#pragma unroll
        for (int j = 0; j < 4; j++) {
            int rb = (wn * 32 + j * 8 + g) * STRU + s8 + cq;
            uint32_t bh0 = Vhi[rb], bh1 = Vhi[rb + 4];
            uint32_t bl0 = Vlo[rb], bl1 = Vlo[rb + 4];
#pragma unroll
            for (int i = 0; i < 4; i++)
                mma_fp16(acc[i][j], a[i][0], a[i][1], a[i][2], a[i][3], bh0, bh1);
#pragma unroll
            for (int i = 0; i < 4; i++)
                mma_fp16(acc[i][j], a[i][0], a[i][1], a[i][2], a[i][3], bl0, bl1);
        }
    }
}

__global__ __launch_bounds__(256, 2) void pv_kernel(
    const float* __restrict__ P, float* __restrict__ out)
{
    extern __shared__ uint32_t smemU[];
    const uint32_t sbase = (uint32_t)__cvta_generic_to_shared(smemU);

    const int b     = blockIdx.z;
    const int qBase = blockIdx.y * 128;
    const int nBase = blockIdx.x * 128;

    const int tid  = threadIdx.x;
    const int lane = tid & 31;
    const int w    = tid >> 5;
    const int wm   = w >> 2;
    const int wn   = w & 3;
    const int g    = lane >> 2;
    const int cq   = lane & 3;

    float acc[4][4][4];
#pragma unroll
    for (int i = 0; i < 4; i++)
#pragma unroll
        for (int j = 0; j < 4; j++)
#pragma unroll
            for (int r = 0; r < 4; r++) acc[i][j][r] = 0.0f;

    const float* Pb = P + (size_t)b * N_ * N_;
    const uint32_t* Vhi_g = g_Vthi + (size_t)b * C_ * (N_ / 2);
    const uint32_t* Vlo_g = g_Vtlo + (size_t)b * C_ * (N_ / 2);
    const int nChunks = N_ / KC;

    pv_load_async(Pb, Vhi_g, Vlo_g, qBase, nBase, 0, sbase, tid);
    for (int c = 0; c < nChunks; c++) {
        const int cur = c & 1;
        if (c + 1 < nChunks) {
            const int nxt = cur ^ 1;
            pv_load_async(Pb, Vhi_g, Vlo_g, qBase, nBase, (c + 1) * KC,
                          sbase + (uint32_t)(nxt * PV_STAGE_U) * 4, tid);
            asm volatile("cp.async.wait_group 1;" ::: "memory");
        } else {
            asm volatile("cp.async.wait_group 0;" ::: "memory");
        }
        __syncthreads();
        const uint32_t* st = smemU + cur * PV_STAGE_U;
        pv_compute_chunk(reinterpret_cast<const float*>(st),
                         st + TILEF, st + TILEF + TILEU,
                         acc, wm, wn, g, cq);
        __syncthreads();
    }

#pragma unroll
    for (int i = 0; i < 4; i++) {
        int r0 = qBase + wm * 64 + i * 16 + g;
        int r1 = r0 + 8;
#pragma unroll
        for (int j = 0; j < 4; j++) {
            int col = nBase + wn * 32 + j * 8 + 2 * cq;
            size_t i0 = ((size_t)b * N_ + r0) * C_ + col;
            size_t i1 = ((size_t)b * N_ + r1) * C_ + col;
            *reinterpret_cast<float2*>(&out[i0]) = make_float2(acc[i][j][0], acc[i][j][1]);
            *reinterpret_cast<float2*>(&out[i1]) = make_float2(acc[i][j][2], acc[i][j][3]);
        }
    }
}

// ---------------------------------------------------------------------------
// Launch
// ---------------------------------------------------------------------------
extern "C" void kernel_launch(void* const* d_in, const int* in_sizes, int n_in,
                              void* d_out, int out_size)
{
    const float* Q    = (const float*)d_in[0];
    const float* K    = (const float*)d_in[1];
    const float* V    = (const float*)d_in[2];
    const int*   mask = (const int*)d_in[3];
    const float* dis  = (const float*)d_in[4];

    float* out    = (float*)d_out;
    float* p_val  = out;                          // [B, N, C]
    float* p_attn = out + (size_t)B_ * N_ * C_;   // [B, N, N]

    cudaFuncSetAttribute(qk_scores_kernel,
                         cudaFuncAttributeMaxDynamicSharedMemorySize, DYN_QK);
    cudaFuncSetAttribute(pv_kernel,
                         cudaFuncAttributeMaxDynamicSharedMemorySize, DYN_PV);

    const int packBlocks = (B_ * N_ * C_ / 4 + 255) / 256;
    pack_qk_kernel<<<packBlocks, 256>>>(Q, K);
    transpose_v_kernel<<<dim3(C_ / 32, N_ / 32, B_), 256>>>(V);
    qk_scores_kernel<<<dim3(N_ / 128, N_ / 128, B_), 256, DYN_QK>>>(dis, mask, p_attn);
    softmax_kernel<<<B_ * N_, 256>>>(p_attn);
    pv_kernel<<<dim3(C_ / 128, N_ / 128, B_), 256, DYN_PV>>>(p_attn, p_val);
}

// round 17
// speedup vs baseline: 1.3430x; 1.2420x over previous
#include <cuda_runtime.h>
#include <cuda_fp16.h>
#include <math.h>
#include <stdint.h>

#define B_ 16
#define N_ 1024
#define C_ 256

#define KC    32                   // k-chunk in floats (= 16 fp16x2 pairs)
#define KP    16                   // k-chunk in u32 pairs
#define STRU  20                   // plane smem row stride in u32
#define TILEU (128 * STRU)         // u32 per plane tile (10240 B)
#define STRF  36                   // fp32 smem row stride (floats)
#define TILEF (128 * STRF)         // floats per fp32 tile (18432 B)

#define DYN_QK (2 * 3 * TILEU * 4)             // 61440 B (Qhi,Qlo,Kh per stage)
#define PV_STAGE_U (TILEF + TILEU)             // u32 per pv stage (28672 B)
#define DYN_PV (2 * PV_STAGE_U * 4)            // 57344 B

// fp16x2 planes
static __device__ uint32_t g_Qhi[(size_t)B_ * N_ * C_ / 2];
static __device__ uint32_t g_Qlo[(size_t)B_ * N_ * C_ / 2];
static __device__ uint32_t g_Kh [(size_t)B_ * N_ * C_ / 2];
static __device__ uint32_t g_Vth[(size_t)B_ * C_ * N_ / 2];   // V^T fp16 [b][c][n/2]

// ---------------------------------------------------------------------------
// mma.sync m16n8k16 f16, row.col, fp32 accumulate
// ---------------------------------------------------------------------------
__device__ __forceinline__ void mma_fp16(float* d,
                                         uint32_t a0, uint32_t a1,
                                         uint32_t a2, uint32_t a3,
                                         uint32_t b0, uint32_t b1) {
    asm volatile(
        "mma.sync.aligned.m16n8k16.row.col.f32.f16.f16.f32 "
        "{%0,%1,%2,%3}, {%4,%5,%6,%7}, {%8,%9}, {%0,%1,%2,%3};"
        : "+f"(d[0]), "+f"(d[1]), "+f"(d[2]), "+f"(d[3])
        : "r"(a0), "r"(a1), "r"(a2), "r"(a3), "r"(b0), "r"(b1));
}

// fp32 pair -> packed f16x2 (low half = v.x)
__device__ __forceinline__ uint32_t cvt_f16x2(float2 v) {
    uint32_t r;
    asm("cvt.rn.f16x2.f32 %0, %1, %2;" : "=r"(r) : "f"(v.y), "f"(v.x));
    return r;
}

// fp16 split: hi = RN(v), lo = RN(v - hi)
__device__ __forceinline__ void pack_split_f16(float2 v, uint32_t& hi, uint32_t& lo) {
    hi = cvt_f16x2(v);
    __half2 h = *reinterpret_cast<__half2*>(&hi);
    float lx = v.x - __low2float(h);
    float ly = v.y - __high2float(h);
    lo = cvt_f16x2(make_float2(lx, ly));
}

__device__ __forceinline__ void cp16(uint32_t saddr, const void* g) {
    asm volatile("cp.async.ca.shared.global [%0], [%1], 16;"
                 :: "r"(saddr), "l"(g) : "memory");
}

// ---------------------------------------------------------------------------
// Kernel A: pack Q (hi/lo) and K (rounded) fp16 planes
// ---------------------------------------------------------------------------
__global__ __launch_bounds__(256) void pack_qk_kernel(
    const float* __restrict__ Q, const float* __restrict__ K)
{
    size_t idx = (size_t)blockIdx.x * 256 + threadIdx.x;   // float4 index
    const size_t total = (size_t)B_ * N_ * C_ / 4;
    if (idx >= total) return;
    float4 q = *reinterpret_cast<const float4*>(Q + idx * 4);
    float4 k = *reinterpret_cast<const float4*>(K + idx * 4);
    uint32_t h0, l0, h1, l1;
    pack_split_f16(make_float2(q.x, q.y), h0, l0);
    pack_split_f16(make_float2(q.z, q.w), h1, l1);
    *reinterpret_cast<uint2*>(&g_Qhi[idx * 2]) = make_uint2(h0, h1);
    *reinterpret_cast<uint2*>(&g_Qlo[idx * 2]) = make_uint2(l0, l1);
    uint32_t kh0 = cvt_f16x2(make_float2(k.x, k.y));
    uint32_t kh1 = cvt_f16x2(make_float2(k.z, k.w));
    *reinterpret_cast<uint2*>(&g_Kh[idx * 2]) = make_uint2(kh0, kh1);
}

// ---------------------------------------------------------------------------
// Kernel B: transpose V -> single fp16 plane [b][c][n/2]
// ---------------------------------------------------------------------------
__global__ __launch_bounds__(256) void transpose_v_kernel(const float* __restrict__ V)
{
    __shared__ float t[32][33];
    const int b  = blockIdx.z;
    const int n0 = blockIdx.y * 32;
    const int c0 = blockIdx.x * 32;
    const float* Vb = V + (size_t)b * N_ * C_;
    const int x = threadIdx.x & 31;
    const int y = threadIdx.x >> 5;
#pragma unroll
    for (int dy = 0; dy < 32; dy += 8)
        t[y + dy][x] = Vb[(size_t)(n0 + y + dy) * C_ + c0 + x];
    __syncthreads();
    const int tid = threadIdx.x;
#pragma unroll
    for (int e = 0; e < 2; e++) {
        int idx = tid + e * 256;
        int cl  = idx >> 4;
        int p   = idx & 15;
        size_t o = ((size_t)b * C_ + c0 + cl) * (N_ / 2) + n0 / 2 + p;
        g_Vth[o] = cvt_f16x2(make_float2(t[2 * p][cl], t[2 * p + 1][cl]));
    }
}

// ===========================================================================
// QK: 2-pass fp16 from planes (Qhi*Kh + Qlo*Kh)
// ===========================================================================
__device__ __forceinline__ void qk_load_async(
    const uint32_t* __restrict__ Qhi, const uint32_t* __restrict__ Qlo,
    const uint32_t* __restrict__ Kh,
    int aBase, int bBase, int k0P, uint32_t sbase, int tid)
{
    const uint32_t* planes[3] = { Qhi, Qlo, Kh };
#pragma unroll
    for (int e = 0; e < 6; e++) {
        int lin  = tid + e * 256;          // 0..1535
        int t    = lin >> 9;               // plane 0..2
        int rem  = lin & 511;
        int row  = rem >> 2;
        int cc   = (rem & 3) * 4;
        int base = (t < 2) ? aBase : bBase;
        uint32_t dst = sbase + (uint32_t)(t * TILEU + row * STRU + cc) * 4;
        cp16(dst, planes[t] + (size_t)(base + row) * (C_ / 2) + k0P + cc);
    }
    asm volatile("cp.async.commit_group;" ::: "memory");
}

__device__ __forceinline__ void qk_compute_chunk(
    const uint32_t* __restrict__ Ahi, const uint32_t* __restrict__ Alo,
    const uint32_t* __restrict__ Bh,
    float acc[4][4][4], int wm, int wn, int g, int cq)
{
#pragma unroll
    for (int s8 = 0; s8 < KP; s8 += 8) {
        const int co = s8 + cq;
        uint32_t ah[4][4], al[4][4];
#pragma unroll
        for (int i = 0; i < 4; i++) {
            int r0 = (wm * 64 + i * 16 + g) * STRU + co;
            int r1 = r0 + 8 * STRU;
            ah[i][0] = Ahi[r0];     al[i][0] = Alo[r0];
            ah[i][1] = Ahi[r1];     al[i][1] = Alo[r1];
            ah[i][2] = Ahi[r0 + 4]; al[i][2] = Alo[r0 + 4];
            ah[i][3] = Ahi[r1 + 4]; al[i][3] = Alo[r1 + 4];
        }
#pragma unroll
        for (int j = 0; j < 4; j++) {
            int rb = (wn * 32 + j * 8 + g) * STRU + co;
            uint32_t b0 = Bh[rb], b1 = Bh[rb + 4];
#pragma unroll
            for (int i = 0; i < 4; i++)
                mma_fp16(acc[i][j], ah[i][0], ah[i][1], ah[i][2], ah[i][3], b0, b1);
#pragma unroll
            for (int i = 0; i < 4; i++)
                mma_fp16(acc[i][j], al[i][0], al[i][1], al[i][2], al[i][3], b0, b1);
        }
    }
}

__global__ __launch_bounds__(256, 2) void qk_scores_kernel(
    const float* __restrict__ dis,
    const int*   __restrict__ mask,
    float* __restrict__ attn)
{
    extern __shared__ uint32_t smem[];
    const uint32_t sbase = (uint32_t)__cvta_generic_to_shared(smem);

    const int b     = blockIdx.z;
    const int qBase = blockIdx.y * 128;
    const int kBase = blockIdx.x * 128;

    const int tid  = threadIdx.x;
    const int lane = tid & 31;
    const int w    = tid >> 5;
    const int wm   = w >> 2;
    const int wn   = w & 3;
    const int g    = lane >> 2;
    const int cq   = lane & 3;

    float acc[4][4][4];
#pragma unroll
    for (int i = 0; i < 4; i++)
#pragma unroll
        for (int j = 0; j < 4; j++)
#pragma unroll
            for (int r = 0; r < 4; r++) acc[i][j][r] = 0.0f;

    const size_t off = (size_t)b * N_ * (C_ / 2);
    const uint32_t* Qhi = g_Qhi + off;
    const uint32_t* Qlo = g_Qlo + off;
    const uint32_t* Kh  = g_Kh + off;
    const int nChunks = C_ / KC;

    qk_load_async(Qhi, Qlo, Kh, qBase, kBase, 0, sbase, tid);
    for (int c = 0; c < nChunks; c++) {
        const int cur = c & 1;
        if (c + 1 < nChunks) {
            const int nxt = cur ^ 1;
            qk_load_async(Qhi, Qlo, Kh, qBase, kBase, (c + 1) * KP,
                          sbase + (uint32_t)(nxt * 3 * TILEU) * 4, tid);
            asm volatile("cp.async.wait_group 1;" ::: "memory");
        } else {
            asm volatile("cp.async.wait_group 0;" ::: "memory");
        }
        __syncthreads();
        const uint32_t* st = smem + cur * 3 * TILEU;
        qk_compute_chunk(st, st + TILEU, st + 2 * TILEU, acc, wm, wn, g, cq);
        __syncthreads();
    }

#pragma unroll
    for (int i = 0; i < 4; i++) {
        int r0 = qBase + wm * 64 + i * 16 + g;
        int r1 = r0 + 8;
#pragma unroll
        for (int j = 0; j < 4; j++) {
            int col = kBase + wn * 32 + j * 8 + 2 * cq;
            size_t i0 = ((size_t)b * N_ + r0) * N_ + col;
            size_t i1 = ((size_t)b * N_ + r1) * N_ + col;
            float2 d0 = *reinterpret_cast<const float2*>(&dis[i0]);
            float2 d1 = *reinterpret_cast<const float2*>(&dis[i1]);
            int2   m0 = *reinterpret_cast<const int2*>(&mask[i0]);
            int2   m1 = *reinterpret_cast<const int2*>(&mask[i1]);
            float2 o0, o1;
            o0.x = m0.x ? -INFINITY : (acc[i][j][0] + d0.x) * 0.0625f;
            o0.y = m0.y ? -INFINITY : (acc[i][j][1] + d0.y) * 0.0625f;
            o1.x = m1.x ? -INFINITY : (acc[i][j][2] + d1.x) * 0.0625f;
            o1.y = m1.y ? -INFINITY : (acc[i][j][3] + d1.y) * 0.0625f;
            *reinterpret_cast<float2*>(&attn[i0]) = o0;
            *reinterpret_cast<float2*>(&attn[i1]) = o1;
        }
    }
}

// ---------------------------------------------------------------------------
// Kernel 2: row softmax (rows of 1024), shuffle-based, float4 I/O
// ---------------------------------------------------------------------------
__global__ __launch_bounds__(256) void softmax_kernel(float* __restrict__ attn)
{
    __shared__ float s1[8], s2[8];
    const size_t base = (size_t)blockIdx.x * N_;
    const int t = threadIdx.x;
    const int w = t >> 5, lane = t & 31;

    float4 v = *reinterpret_cast<const float4*>(&attn[base + t * 4]);

    float m = fmaxf(fmaxf(v.x, v.y), fmaxf(v.z, v.w));
#pragma unroll
    for (int o = 16; o; o >>= 1) m = fmaxf(m, __shfl_xor_sync(0xffffffffu, m, o));
    if (lane == 0) s1[w] = m;
    __syncthreads();
    float M = s1[0];
#pragma unroll
    for (int i = 1; i < 8; i++) M = fmaxf(M, s1[i]);

    float4 p;
    p.x = __expf(v.x - M); p.y = __expf(v.y - M);
    p.z = __expf(v.z - M); p.w = __expf(v.w - M);
    float s = (p.x + p.y) + (p.z + p.w);
#pragma unroll
    for (int o = 16; o; o >>= 1) s += __shfl_xor_sync(0xffffffffu, s, o);
    if (lane == 0) s2[w] = s;
    __syncthreads();
    float S = s2[0];
#pragma unroll
    for (int i = 1; i < 8; i++) S += s2[i];
    float inv = 1.0f / S;

    p.x *= inv; p.y *= inv; p.z *= inv; p.w *= inv;
    *reinterpret_cast<float4*>(&attn[base + t * 4]) = p;
}

// ===========================================================================
// PV: 1-pass fp16. A = attn fp32 (cvt in-loop), B = V fp16 plane.
// ===========================================================================
__device__ __forceinline__ void pv_load_async(
    const float* __restrict__ Pg, const uint32_t* __restrict__ Vh_g,
    int qBase, int nBase, int k0, uint32_t sbase, int tid)
{
#pragma unroll
    for (int e = 0; e < 4; e++) {
        int lin = tid + e * 256;
        int row = lin >> 3;
        int c4  = (lin & 7) * 4;
        uint32_t dst = sbase + (uint32_t)(row * STRF + c4) * 4;
        cp16(dst, &Pg[(size_t)(qBase + row) * N_ + k0 + c4]);
    }
#pragma unroll
    for (int e = 0; e < 2; e++) {
        int lin = tid + e * 256;          // 0..511
        int row = lin >> 2;
        int cc  = (lin & 3) * 4;
        uint32_t dst = sbase + (uint32_t)(TILEF + row * STRU + cc) * 4;
        cp16(dst, Vh_g + (size_t)(nBase + row) * (N_ / 2) + k0 / 2 + cc);
    }
    asm volatile("cp.async.commit_group;" ::: "memory");
}

__device__ __forceinline__ void pv_compute_chunk(
    const float* __restrict__ As, const uint32_t* __restrict__ Vh,
    float acc[4][4][4], int wm, int wn, int g, int cq)
{
#pragma unroll
    for (int s = 0; s < KC; s += 16) {
        const int co = s + 2 * cq;
        const int s8 = s / 2;
        uint32_t a[4][4];
#pragma unroll
        for (int i = 0; i < 4; i++) {
            int r0 = (wm * 64 + i * 16 + g) * STRF + co;
            int r1 = r0 + 8 * STRF;
            a[i][0] = cvt_f16x2(*reinterpret_cast<const float2*>(&As[r0]));
            a[i][1] = cvt_f16x2(*reinterpret_cast<const float2*>(&As[r1]));
            a[i][2] = cvt_f16x2(*reinterpret_cast<const float2*>(&As[r0 + 8]));
            a[i][3] = cvt_f16x2(*reinterpret_cast<const float2*>(&As[r1 + 8]));
        }
#pragma unroll
        for (int j = 0; j < 4; j++) {
            int rb = (wn * 32 + j * 8 + g) * STRU + s8 + cq;
            uint32_t b0 = Vh[rb], b1 = Vh[rb + 4];
#pragma unroll
            for (int i = 0; i < 4; i++)
                mma_fp16(acc[i][j], a[i][0], a[i][1], a[i][2], a[i][3], b0, b1);
        }
    }
}

__global__ __launch_bounds__(256, 2) void pv_kernel(
    const float* __restrict__ P, float* __restrict__ out)
{
    extern __shared__ uint32_t smemU[];
    const uint32_t sbase = (uint32_t)__cvta_generic_to_shared(smemU);

    const int b     = blockIdx.z;
    const int qBase = blockIdx.y * 128;
    const int nBase = blockIdx.x * 128;

    const int tid  = threadIdx.x;
    const int lane = tid & 31;
    const int w    = tid >> 5;
    const int wm   = w >> 2;
    const int wn   = w & 3;
    const int g    = lane >> 2;
    const int cq   = lane & 3;

    float acc[4][4][4];
#pragma unroll
    for (int i = 0; i < 4; i++)
#pragma unroll
        for (int j = 0; j < 4; j++)
#pragma unroll
            for (int r = 0; r < 4; r++) acc[i][j][r] = 0.0f;

    const float* Pb = P + (size_t)b * N_ * N_;
    const uint32_t* Vh_g = g_Vth + (size_t)b * C_ * (N_ / 2);
    const int nChunks = N_ / KC;

    pv_load_async(Pb, Vh_g, qBase, nBase, 0, sbase, tid);
    for (int c = 0; c < nChunks; c++) {
        const int cur = c & 1;
        if (c + 1 < nChunks) {
            const int nxt = cur ^ 1;
            pv_load_async(Pb, Vh_g, qBase, nBase, (c + 1) * KC,
                          sbase + (uint32_t)(nxt * PV_STAGE_U) * 4, tid);
            asm volatile("cp.async.wait_group 1;" ::: "memory");
        } else {
            asm volatile("cp.async.wait_group 0;" ::: "memory");
        }
        __syncthreads();
        const uint32_t* st = smemU + cur * PV_STAGE_U;
        pv_compute_chunk(reinterpret_cast<const float*>(st), st + TILEF,
                         acc, wm, wn, g, cq);
        __syncthreads();
    }

#pragma unroll
    for (int i = 0; i < 4; i++) {
        int r0 = qBase + wm * 64 + i * 16 + g;
        int r1 = r0 + 8;
#pragma unroll
        for (int j = 0; j < 4; j++) {
            int col = nBase + wn * 32 + j * 8 + 2 * cq;
            size_t i0 = ((size_t)b * N_ + r0) * C_ + col;
            size_t i1 = ((size_t)b * N_ + r1) * C_ + col;
            *reinterpret_cast<float2*>(&out[i0]) = make_float2(acc[i][j][0], acc[i][j][1]);
            *reinterpret_cast<float2*>(&out[i1]) = make_float2(acc[i][j][2], acc[i][j][3]);
        }
    }
}

// ---------------------------------------------------------------------------
// Launch
// ---------------------------------------------------------------------------
extern "C" void kernel_launch(void* const* d_in, const int* in_sizes, int n_in,
                              void* d_out, int out_size)
{
    const float* Q    = (const float*)d_in[0];
    const float* K    = (const float*)d_in[1];
    const float* V    = (const float*)d_in[2];
    const int*   mask = (const int*)d_in[3];
    const float* dis  = (const float*)d_in[4];

    float* out    = (float*)d_out;
    float* p_val  = out;                          // [B, N, C]
    float* p_attn = out + (size_t)B_ * N_ * C_;   // [B, N, N]

    cudaFuncSetAttribute(qk_scores_kernel,
                         cudaFuncAttributeMaxDynamicSharedMemorySize, DYN_QK);
    cudaFuncSetAttribute(pv_kernel,
                         cudaFuncAttributeMaxDynamicSharedMemorySize, DYN_PV);

    const int packBlocks = (B_ * N_ * C_ / 4 + 255) / 256;
    pack_qk_kernel<<<packBlocks, 256>>>(Q, K);
    transpose_v_kernel<<<dim3(C_ / 32, N_ / 32, B_), 256>>>(V);
    qk_scores_kernel<<<dim3(N_ / 128, N_ / 128, B_), 256, DYN_QK>>>(dis, mask, p_attn);
    softmax_kernel<<<B_ * N_, 256>>>(p_attn);
    pv_kernel<<<dim3(C_ / 128, N_ / 128, B_), 256, DYN_PV>>>(p_attn, p_val);
}